// round 8
// baseline (speedup 1.0000x reference)
#include <cuda_runtime.h>
#include <cuda_bf16.h>

#define NUM_CLASSES 10

// Fast-family variant of the reproducible 4.608us R4 kernel:
// one CTA per batch, 96 threads (3 warps), each thread loads a float2
// (96 x 2 = 192 patch elements), warp-reduces, combines 3 partials via
// smem with the same two-barrier structure, lanes 0..9 write the logits.
__global__ __launch_bounds__(96, 8)
void ldc_kernel(const float* __restrict__ x, float* __restrict__ out) {
    const unsigned b   = blockIdx.x;      // batch 0..63
    const unsigned tid = threadIdx.x;     // 0..95

    // tid -> (c, r, colpair): c = tid/32, within-patch pair = tid%32
    const unsigned c  = tid >> 5;         // channel 0..2
    const unsigned w  = tid & 31u;        // pair index 0..31
    const unsigned r  = w >> 2;           // row 0..7
    const unsigned cp = w & 3u;           // col pair 0..3 (cols 2*cp, 2*cp+1)

    // 32-bit offset: ((b*3 + c) << 18) + (r << 9) + 2*cp ; 8B-aligned.
    const unsigned idx = ((b * 3u + c) << 18) + (r << 9) + (cp << 1);
    const float2 a = *(const float2*)(x + idx);
    float v = a.x + a.y;

    #pragma unroll
    for (int off = 16; off > 0; off >>= 1)
        v += __shfl_down_sync(0xFFFFFFFFu, v, off);

    __shared__ float partial[3];
    __shared__ int s_pred;
    const unsigned warp = tid >> 5;
    if ((tid & 31u) == 0) partial[warp] = v;
    __syncthreads();

    if (tid == 0) {
        float total = partial[0] + partial[1] + partial[2];
        float mean = total / 192.0f;
        // Python int() truncates toward zero; % with positive modulus is non-negative.
        int t = (int)truncf(mean * 10.0f);
        int pred = t % NUM_CLASSES;
        if (pred < 0) pred += NUM_CLASSES;
        s_pred = pred;
    }
    __syncthreads();

    if (tid < NUM_CLASSES)
        out[b * NUM_CLASSES + tid] = ((int)tid == s_pred) ? 10.0f : 0.0f;
}

extern "C" void kernel_launch(void* const* d_in, const int* in_sizes, int n_in,
                              void* d_out, int out_size) {
    const float* x = (const float*)d_in[0];
    float* out = (float*)d_out;
    ldc_kernel<<<64, 96>>>(x, out);
}